// round 5
// baseline (speedup 1.0000x reference)
#include <cuda_runtime.h>
#include <cuda_bf16.h>
#include <cstdint>

// Focal loss (log10 variant) mean over 28.3M elems. HBM-bound: 226.5 MB read.
// Dynamic chunk-stealing persistent kernel: eliminates end-of-kernel CTA
// spread (the measured 27% DRAM idle) while staying bit-deterministic:
// chunk partials are computed in a fixed lane/iteration order no matter which
// block grabs them, stored per-chunk, and summed in fixed index order by the
// last-arriving block.

#define NTHREADS    256
#define NBLOCKS     1184          // 148 SMs * 8 blocks
#define CHUNK_ITER  6
#define CHUNK_VEC   (NTHREADS * CHUNK_ITER)   // 1536 vec4 per chunk
#define MAX_CHUNKS  8192

__device__ float        g_chunk_part[MAX_CHUNKS + 1];  // +1 = tail slot
__device__ unsigned int g_chunk = 0;
__device__ unsigned int g_count = 0;

__device__ __forceinline__ float focal_elem(float p, int y) {
    bool  pos = (y != 0);
    float pt  = pos ? p : 1.0f - p;
    float om  = 1.0f - pt;
    // -log10(pt) = -log2(pt) * log10(2)
    float lt  = -__log2f(pt) * 0.3010299956639812f;
    float w   = pos ? 0.9f : 0.1f;
    return w * om * om * lt;
}

__device__ __forceinline__ float focal_vec(float4 p, int4 t) {
    float a = focal_elem(p.x, t.x);
    a += focal_elem(p.y, t.y);
    a += focal_elem(p.z, t.z);
    a += focal_elem(p.w, t.w);
    return a;
}

__device__ __forceinline__ float block_reduce(float acc, float* smem) {
    // returns full-block sum on thread 0 (garbage elsewhere)
    #pragma unroll
    for (int off = 16; off > 0; off >>= 1)
        acc += __shfl_xor_sync(0xFFFFFFFFu, acc, off);
    int lane = threadIdx.x & 31;
    int wid  = threadIdx.x >> 5;
    if (lane == 0) smem[wid] = acc;
    __syncthreads();
    float v = 0.0f;
    if (threadIdx.x == 0) {
        #pragma unroll
        for (int w = 0; w < NTHREADS / 32; w++) v += smem[w];
    }
    return v;
}

__global__ void __launch_bounds__(NTHREADS, 8)
focal_steal_kernel(const float4* __restrict__ p4,
                   const int4*   __restrict__ t4,
                   int nchunks, int nvec, int ntail,
                   const float* __restrict__ p_tail,
                   const int*   __restrict__ t_tail,
                   float* __restrict__ out, float inv_n) {
    __shared__ float        s_red[NTHREADS / 32];
    __shared__ unsigned int s_next;
    __shared__ bool         s_last;

    const int tid = threadIdx.x;

    // ---- block 0: leftover vec4s beyond full chunks + scalar tail -> slot nchunks
    if (blockIdx.x == 0) {
        float acc = 0.0f;
        for (int i = nchunks * CHUNK_VEC + tid; i < nvec; i += NTHREADS) {
            float4 p = p4[i];
            int4   t = t4[i];
            acc += focal_vec(p, t);
        }
        for (int k = tid; k < ntail; k += NTHREADS)
            acc += focal_elem(p_tail[k], t_tail[k]);
        float v = block_reduce(acc, s_red);
        if (tid == 0) g_chunk_part[nchunks] = v;
        __syncthreads();
    }

    // ---- first grab
    if (tid == 0) s_next = atomicAdd(&g_chunk, 1u);
    __syncthreads();
    unsigned int c = s_next;

    // ---- steal loop
    while (c < (unsigned int)nchunks) {
        // grab next chunk early to hide atomic latency
        if (tid == 0) s_next = atomicAdd(&g_chunk, 1u);

        int base = (int)c * CHUNK_VEC + tid;

        // depth-2 prefetch pipeline over CHUNK_ITER contiguous strides
        float4 pc = p4[base];
        int4   tc = t4[base];
        float  acc = 0.0f;
        #pragma unroll
        for (int k = 1; k < CHUNK_ITER; k++) {
            float4 pn = p4[base + k * NTHREADS];
            int4   tn = t4[base + k * NTHREADS];
            acc += focal_vec(pc, tc);
            pc = pn;
            tc = tn;
        }
        acc += focal_vec(pc, tc);

        float v = block_reduce(acc, s_red);
        if (tid == 0) g_chunk_part[c] = v;
        __syncthreads();            // s_next visible, s_red reusable
        c = s_next;
    }

    // ---- arrival counting; last block does deterministic final sum
    if (tid == 0) {
        __threadfence();
        unsigned int prev = atomicAdd(&g_count, 1u);
        s_last = (prev == (unsigned int)(gridDim.x - 1));
    }
    __syncthreads();

    if (s_last) {
        int total = nchunks + 1;    // + tail slot
        float v = 0.0f;
        for (int k = tid; k < total; k += NTHREADS)
            v += g_chunk_part[k];

        #pragma unroll
        for (int off = 16; off > 0; off >>= 1)
            v += __shfl_xor_sync(0xFFFFFFFFu, v, off);

        int lane = tid & 31;
        int wid  = tid >> 5;
        if (lane == 0) s_red[wid] = v;
        __syncthreads();

        if (wid == 0) {
            float s = (lane < NTHREADS / 32) ? s_red[lane] : 0.0f;
            #pragma unroll
            for (int off = 4; off > 0; off >>= 1)
                s += __shfl_xor_sync(0xFFFFFFFFu, s, off);
            if (lane == 0) {
                out[0] = s * inv_n;
                g_count = 0;        // reset for next graph replay
                g_chunk = 0;
                __threadfence();
            }
        }
    }
}

extern "C" void kernel_launch(void* const* d_in, const int* in_sizes, int n_in,
                              void* d_out, int out_size) {
    const float* p = (const float*)d_in[0];
    const int*   t = (const int*)d_in[1];
    int n = in_sizes[0];

    int nvec    = n >> 2;
    int ntail   = n - (nvec << 2);
    int nchunks = nvec / CHUNK_VEC;           // full chunks only
    if (nchunks > MAX_CHUNKS) nchunks = MAX_CHUNKS;

    focal_steal_kernel<<<NBLOCKS, NTHREADS>>>(
        (const float4*)p, (const int4*)t,
        nchunks, nvec, ntail,
        p + (nvec << 2), t + (nvec << 2),
        (float*)d_out, 1.0f / (float)n);
}

// round 7
// speedup vs baseline: 1.0888x; 1.0888x over previous
#include <cuda_runtime.h>
#include <cuda_bf16.h>
#include <cstdint>

// Focal loss (log10 variant) mean over 28.3M elems. HBM-bound: 226.5 MB read.
// R4 skeleton (uninterrupted grid-stride stream + depth-2 prefetch, fused
// deterministic last-block reduce) at FULL residency with exact balance:
// 1152 blocks x 256 thr = 294912 threads -> exactly 24 vec4/thread, all
// blocks resident in one wave (launch_bounds(256,8) pins regs <= 32).
// (Resubmission of R6 kernel — previous round died to a container infra
// failure before execution.)

#define NBLOCKS   1152
#define NTHREADS  256

__device__ float        g_partials[NBLOCKS];
__device__ unsigned int g_count = 0;

__device__ __forceinline__ float focal_elem(float p, int y) {
    bool  pos = (y != 0);
    float pt  = pos ? p : 1.0f - p;
    float om  = 1.0f - pt;
    // -log10(pt) = -log2(pt) * log10(2)
    float lt  = -__log2f(pt) * 0.3010299956639812f;
    float w   = pos ? 0.9f : 0.1f;
    return w * om * om * lt;
}

__device__ __forceinline__ float focal_vec(float4 p, int4 t) {
    float a = focal_elem(p.x, t.x);
    a += focal_elem(p.y, t.y);
    a += focal_elem(p.z, t.z);
    a += focal_elem(p.w, t.w);
    return a;
}

__global__ void __launch_bounds__(NTHREADS, 8)
focal_fused_kernel(const float4* __restrict__ p4,
                   const int4*   __restrict__ t4,
                   int nvec, int ntail,
                   const float* __restrict__ p_tail,
                   const int*   __restrict__ t_tail,
                   float* __restrict__ out, float inv_n) {
    const int stride = gridDim.x * blockDim.x;
    int i = blockIdx.x * blockDim.x + threadIdx.x;

    float acc = 0.0f;

    if (i < nvec) {
        // prime the pipeline
        float4 pc = p4[i];
        int4   tc = t4[i];
        int    in = i + stride;

        while (in < nvec) {
            // issue next loads before consuming current values
            float4 pn = p4[in];
            int4   tn = t4[in];
            acc += focal_vec(pc, tc);
            pc = pn;
            tc = tn;
            in += stride;
        }
        acc += focal_vec(pc, tc);
    }

    if (blockIdx.x == 0) {
        for (int k = threadIdx.x; k < ntail; k += blockDim.x)
            acc += focal_elem(p_tail[k], t_tail[k]);
    }

    // intra-block reduce
    #pragma unroll
    for (int off = 16; off > 0; off >>= 1)
        acc += __shfl_xor_sync(0xFFFFFFFFu, acc, off);

    __shared__ float smem[NTHREADS / 32];
    int lane = threadIdx.x & 31;
    int wid  = threadIdx.x >> 5;
    if (lane == 0) smem[wid] = acc;
    __syncthreads();

    __shared__ bool s_last;
    if (threadIdx.x == 0) {
        float v = 0.0f;
        #pragma unroll
        for (int w = 0; w < NTHREADS / 32; w++) v += smem[w];
        g_partials[blockIdx.x] = v;
        __threadfence();
        unsigned int prev = atomicAdd(&g_count, 1u);
        s_last = (prev == (unsigned int)(gridDim.x - 1));
    }
    __syncthreads();

    if (s_last) {
        // deterministic final reduction: fixed per-thread order, then tree
        float v = 0.0f;
        #pragma unroll
        for (int k = threadIdx.x; k < NBLOCKS; k += NTHREADS)
            v += g_partials[k];

        #pragma unroll
        for (int off = 16; off > 0; off >>= 1)
            v += __shfl_xor_sync(0xFFFFFFFFu, v, off);

        if (lane == 0) smem[wid] = v;
        __syncthreads();

        if (wid == 0) {
            float s = (lane < NTHREADS / 32) ? smem[lane] : 0.0f;
            #pragma unroll
            for (int off = 4; off > 0; off >>= 1)
                s += __shfl_xor_sync(0xFFFFFFFFu, s, off);
            if (lane == 0) {
                out[0] = s * inv_n;
                g_count = 0;           // reset for next graph replay
                __threadfence();
            }
        }
    }
}

extern "C" void kernel_launch(void* const* d_in, const int* in_sizes, int n_in,
                              void* d_out, int out_size) {
    const float* p = (const float*)d_in[0];
    const int*   t = (const int*)d_in[1];
    int n = in_sizes[0];

    int nvec  = n >> 2;
    int ntail = n - (nvec << 2);

    focal_fused_kernel<<<NBLOCKS, NTHREADS>>>(
        (const float4*)p, (const int4*)t, nvec, ntail,
        p + (nvec << 2), t + (nvec << 2),
        (float*)d_out, 1.0f / (float)n);
}